// round 1
// baseline (speedup 1.0000x reference)
#include <cuda_runtime.h>

#define IN_DIM 128
#define OUT_DIM 32
#define NMAX 100000

// Scratch (device-global statics: allocation-free per harness rules)
__device__ float g_z[NMAX * OUT_DIM];      // z = h @ W_fc
__device__ float g_el[NMAX];               // z @ a_l
__device__ float g_er[NMAX];               // z @ a_r
__device__ float g_esum[NMAX];             // sum of exp(e) per dst
__device__ float g_hacc[NMAX * OUT_DIM];   // sum of exp(e)*z[src] per dst
__device__ float g_stats[2 * OUT_DIM];     // per-channel sum, sumsq
__device__ float g_bn[2 * OUT_DIM];        // per-channel scale, shift

// ---------------------------------------------------------------------------
// K0: zero the accumulators (atomics require fresh zeros every replay)
// ---------------------------------------------------------------------------
__global__ void k_zero(int n) {
    int total = n * OUT_DIM;
    int stride = gridDim.x * blockDim.x;
    for (int i = blockIdx.x * blockDim.x + threadIdx.x; i < total; i += stride) {
        g_hacc[i] = 0.0f;
        if (i < n) g_esum[i] = 0.0f;
        if (i < 2 * OUT_DIM) g_stats[i] = 0.0f;
    }
}

// ---------------------------------------------------------------------------
// K1: z = h @ W_fc ; el = z@a_l ; er = z@a_r
// Warp processes 4 nodes at a time (W-LDS amortized 4x). Lane = output col.
// ---------------------------------------------------------------------------
__global__ void __launch_bounds__(256) k_gemm(
    const float* __restrict__ h, const float* __restrict__ Wfc,
    const float* __restrict__ Wa, int n)
{
    __shared__ float Ws[IN_DIM * OUT_DIM];        // 16 KB
    __shared__ float4 hs4[8][4 * 32];             // 16 KB, per-warp staging

    for (int i = threadIdx.x; i < IN_DIM * OUT_DIM; i += blockDim.x)
        Ws[i] = Wfc[i];
    __syncthreads();

    const int lane = threadIdx.x & 31;
    const int wid  = threadIdx.x >> 5;
    const int gw   = (blockIdx.x * blockDim.x + threadIdx.x) >> 5;
    const int nw   = (gridDim.x * blockDim.x) >> 5;

    const float al = Wa[lane];
    const float ar = Wa[OUT_DIM + lane];
    float4* hsw = hs4[wid];

    const int ngroups = (n + 3) >> 2;
    for (int g = gw; g < ngroups; g += nw) {
        const int base = g * 4;
        // stage 4 h-rows (each row = 32 float4, one per lane)
        #pragma unroll
        for (int i = 0; i < 4; i++) {
            int node = base + i;
            if (node < n)
                hsw[i * 32 + lane] =
                    reinterpret_cast<const float4*>(h + (size_t)node * IN_DIM)[lane];
        }
        __syncwarp();

        float acc0 = 0.f, acc1 = 0.f, acc2 = 0.f, acc3 = 0.f;
        #pragma unroll 8
        for (int k4 = 0; k4 < 32; k4++) {
            const float w0 = Ws[(k4 * 4 + 0) * 32 + lane];
            const float w1 = Ws[(k4 * 4 + 1) * 32 + lane];
            const float w2 = Ws[(k4 * 4 + 2) * 32 + lane];
            const float w3 = Ws[(k4 * 4 + 3) * 32 + lane];
            const float4 h0 = hsw[0 * 32 + k4];
            const float4 h1 = hsw[1 * 32 + k4];
            const float4 h2 = hsw[2 * 32 + k4];
            const float4 h3 = hsw[3 * 32 + k4];
            acc0 = fmaf(h0.x, w0, acc0); acc0 = fmaf(h0.y, w1, acc0);
            acc0 = fmaf(h0.z, w2, acc0); acc0 = fmaf(h0.w, w3, acc0);
            acc1 = fmaf(h1.x, w0, acc1); acc1 = fmaf(h1.y, w1, acc1);
            acc1 = fmaf(h1.z, w2, acc1); acc1 = fmaf(h1.w, w3, acc1);
            acc2 = fmaf(h2.x, w0, acc2); acc2 = fmaf(h2.y, w1, acc2);
            acc2 = fmaf(h2.z, w2, acc2); acc2 = fmaf(h2.w, w3, acc2);
            acc3 = fmaf(h3.x, w0, acc3); acc3 = fmaf(h3.y, w1, acc3);
            acc3 = fmaf(h3.z, w2, acc3); acc3 = fmaf(h3.w, w3, acc3);
        }

        float zz[4] = {acc0, acc1, acc2, acc3};
        #pragma unroll
        for (int i = 0; i < 4; i++) {
            int node = base + i;
            if (node >= n) break;
            float z = zz[i];
            g_z[node * OUT_DIM + lane] = z;
            float vl = z * al;
            float vr = z * ar;
            #pragma unroll
            for (int off = 16; off; off >>= 1) {
                vl += __shfl_xor_sync(0xffffffffu, vl, off);
                vr += __shfl_xor_sync(0xffffffffu, vr, off);
            }
            if (lane == 0) { g_el[node] = vl; g_er[node] = vr; }
        }
        __syncwarp();
    }
}

// ---------------------------------------------------------------------------
// K2: single edge pass.
//   p = exp(lrelu(el[s]+er[d]))        (max-subtraction is shift-invariant
//                                       in alpha and |e|<~6, so omitted)
//   esum[d]   += p
//   hacc[d,:] += p * z[s,:]
// Warp per edge, lane = channel -> coalesced 128B gather + 128B RED burst.
// ---------------------------------------------------------------------------
__global__ void __launch_bounds__(256) k_edges(
    const int* __restrict__ src, const int* __restrict__ dst, int nedges)
{
    const int lane = threadIdx.x & 31;
    const int gw   = (blockIdx.x * blockDim.x + threadIdx.x) >> 5;
    const int nw   = (gridDim.x * blockDim.x) >> 5;

    for (int e = gw; e < nedges; e += nw) {
        const int s = src[e];
        const int d = dst[e];
        float ee = g_el[s] + g_er[d];
        ee = (ee >= 0.0f) ? ee : 0.01f * ee;
        const float p = __expf(ee);
        if (lane == 0) atomicAdd(&g_esum[d], p);
        const float v = p * g_z[s * OUT_DIM + lane];
        atomicAdd(&g_hacc[d * OUT_DIM + lane], v);
    }
}

// ---------------------------------------------------------------------------
// K3: h_out = hacc / esum (0 if no incoming edges); partial BN stats.
// Each warp covers one node per step; lane == channel (stride % 32 == 0).
// ---------------------------------------------------------------------------
__global__ void __launch_bounds__(256) k_final(float* __restrict__ out, int n)
{
    const int lane = threadIdx.x & 31;
    const int total = n * OUT_DIM;
    const int stride = gridDim.x * blockDim.x;
    float s = 0.f, sq = 0.f;
    for (int i = blockIdx.x * blockDim.x + threadIdx.x; i < total; i += stride) {
        const int node = i >> 5;
        const float es = g_esum[node];
        const float v = (es > 0.0f) ? g_hacc[i] / es : 0.0f;
        out[i] = v;
        s += v;
        sq += v * v;
    }
    atomicAdd(&g_stats[lane], s);
    atomicAdd(&g_stats[OUT_DIM + lane], sq);
}

// ---------------------------------------------------------------------------
// K4: fold stats into per-channel affine (scale, shift)
// ---------------------------------------------------------------------------
__global__ void k_bn(const float* __restrict__ gamma,
                     const float* __restrict__ beta, int n)
{
    const int t = threadIdx.x;
    const float inv_n = 1.0f / (float)n;
    const float mean = g_stats[t] * inv_n;
    const float var  = g_stats[OUT_DIM + t] * inv_n - mean * mean;
    const float sc   = gamma[t] * rsqrtf(var + 1e-5f);
    g_bn[t] = sc;
    g_bn[OUT_DIM + t] = beta[t] - mean * sc;
}

// ---------------------------------------------------------------------------
// K5: apply BN affine + ELU in place on out
// ---------------------------------------------------------------------------
__global__ void __launch_bounds__(256) k_elu(float* __restrict__ out, int n)
{
    const int total = n * OUT_DIM;
    const int stride = gridDim.x * blockDim.x;
    for (int i = blockIdx.x * blockDim.x + threadIdx.x; i < total; i += stride) {
        const int t = i & 31;
        const float x = out[i] * g_bn[t] + g_bn[OUT_DIM + t];
        out[i] = (x > 0.0f) ? x : expm1f(x);
    }
}

// ---------------------------------------------------------------------------
extern "C" void kernel_launch(void* const* d_in, const int* in_sizes, int n_in,
                              void* d_out, int out_size)
{
    const float* h     = (const float*)d_in[0];
    const float* Wfc   = (const float*)d_in[1];
    const float* Wa    = (const float*)d_in[2];
    const float* gamma = (const float*)d_in[3];
    const float* beta  = (const float*)d_in[4];
    const int*   src   = (const int*)d_in[5];
    const int*   dst   = (const int*)d_in[6];

    const int n      = in_sizes[0] / IN_DIM;   // 100000
    const int nedges = in_sizes[5];            // 1600000
    float* out = (float*)d_out;

    k_zero <<<1024, 256>>>(n);
    k_gemm <<<1480, 256>>>(h, Wfc, Wa, n);
    k_edges<<<4096, 256>>>(src, dst, nedges);
    k_final<<<1024, 256>>>(out, n);
    k_bn   <<<1, OUT_DIM>>>(gamma, beta, n);
    k_elu  <<<1024, 256>>>(out, n);
}

// round 2
// speedup vs baseline: 1.8496x; 1.8496x over previous
#include <cuda_runtime.h>

#define IN_DIM 128
#define OUT_DIM 32
#define NMAX 100000

__device__ float g_z[NMAX * OUT_DIM];      // z = h @ W_fc
__device__ float g_el[NMAX];               // z @ a_l
__device__ float g_er[NMAX];               // z @ a_r
__device__ float g_esum[NMAX];             // sum exp(e) per dst -> inverted in place
__device__ float g_hacc[NMAX * OUT_DIM];   // sum exp(e)*z[src] per dst
__device__ float g_stats[2 * OUT_DIM];     // channel sum, sumsq
__device__ float g_bn[2 * OUT_DIM];        // channel scale, shift

__device__ __forceinline__ void red_add_v4(float* addr, float4 v) {
    asm volatile("red.global.add.v4.f32 [%0], {%1,%2,%3,%4};"
                 :: "l"(addr), "f"(v.x), "f"(v.y), "f"(v.z), "f"(v.w)
                 : "memory");
}

// ---------------------------------------------------------------------------
// K0: zero accumulators (vectorized)
// ---------------------------------------------------------------------------
__global__ void k_zero(int n) {
    const int total4 = (n * OUT_DIM) / 4;
    const int stride = gridDim.x * blockDim.x;
    float4 z4 = make_float4(0.f, 0.f, 0.f, 0.f);
    float4* hacc4 = reinterpret_cast<float4*>(g_hacc);
    for (int i = blockIdx.x * blockDim.x + threadIdx.x; i < total4; i += stride) {
        hacc4[i] = z4;
        if (i < n) g_esum[i] = 0.0f;
        if (i < 2 * OUT_DIM) g_stats[i] = 0.0f;
    }
}

// ---------------------------------------------------------------------------
// K1: z = h @ W_fc ; el = z@a_l ; er = z@a_r   (warp: 4 nodes, lane = col)
// ---------------------------------------------------------------------------
__global__ void __launch_bounds__(256) k_gemm(
    const float* __restrict__ h, const float* __restrict__ Wfc,
    const float* __restrict__ Wa, int n)
{
    __shared__ float Ws[IN_DIM * OUT_DIM];        // 16 KB
    __shared__ float4 hs4[8][4 * 32];             // 16 KB

    for (int i = threadIdx.x; i < IN_DIM * OUT_DIM; i += blockDim.x)
        Ws[i] = Wfc[i];
    __syncthreads();

    const int lane = threadIdx.x & 31;
    const int wid  = threadIdx.x >> 5;
    const int gw   = (blockIdx.x * blockDim.x + threadIdx.x) >> 5;
    const int nw   = (gridDim.x * blockDim.x) >> 5;

    const float al = Wa[lane];
    const float ar = Wa[OUT_DIM + lane];
    float4* hsw = hs4[wid];

    const int ngroups = (n + 3) >> 2;
    for (int g = gw; g < ngroups; g += nw) {
        const int base = g * 4;
        #pragma unroll
        for (int i = 0; i < 4; i++) {
            int node = base + i;
            if (node < n)
                hsw[i * 32 + lane] =
                    reinterpret_cast<const float4*>(h + (size_t)node * IN_DIM)[lane];
        }
        __syncwarp();

        float acc0 = 0.f, acc1 = 0.f, acc2 = 0.f, acc3 = 0.f;
        #pragma unroll 8
        for (int k4 = 0; k4 < 32; k4++) {
            const float w0 = Ws[(k4 * 4 + 0) * 32 + lane];
            const float w1 = Ws[(k4 * 4 + 1) * 32 + lane];
            const float w2 = Ws[(k4 * 4 + 2) * 32 + lane];
            const float w3 = Ws[(k4 * 4 + 3) * 32 + lane];
            const float4 h0 = hsw[0 * 32 + k4];
            const float4 h1 = hsw[1 * 32 + k4];
            const float4 h2 = hsw[2 * 32 + k4];
            const float4 h3 = hsw[3 * 32 + k4];
            acc0 = fmaf(h0.x, w0, acc0); acc0 = fmaf(h0.y, w1, acc0);
            acc0 = fmaf(h0.z, w2, acc0); acc0 = fmaf(h0.w, w3, acc0);
            acc1 = fmaf(h1.x, w0, acc1); acc1 = fmaf(h1.y, w1, acc1);
            acc1 = fmaf(h1.z, w2, acc1); acc1 = fmaf(h1.w, w3, acc1);
            acc2 = fmaf(h2.x, w0, acc2); acc2 = fmaf(h2.y, w1, acc2);
            acc2 = fmaf(h2.z, w2, acc2); acc2 = fmaf(h2.w, w3, acc2);
            acc3 = fmaf(h3.x, w0, acc3); acc3 = fmaf(h3.y, w1, acc3);
            acc3 = fmaf(h3.z, w2, acc3); acc3 = fmaf(h3.w, w3, acc3);
        }

        float zz[4] = {acc0, acc1, acc2, acc3};
        #pragma unroll
        for (int i = 0; i < 4; i++) {
            int node = base + i;
            if (node >= n) break;
            float z = zz[i];
            g_z[node * OUT_DIM + lane] = z;
            float vl = z * al;
            float vr = z * ar;
            #pragma unroll
            for (int off = 16; off; off >>= 1) {
                vl += __shfl_xor_sync(0xffffffffu, vl, off);
                vr += __shfl_xor_sync(0xffffffffu, vr, off);
            }
            if (lane == 0) { g_el[node] = vl; g_er[node] = vr; }
        }
        __syncwarp();
    }
}

// ---------------------------------------------------------------------------
// K2: edge pass. 4 edges per warp; 8 lanes per edge, each lane owns a float4
// quarter of the 32-channel row. Unnormalized softmax accumulation.
// ---------------------------------------------------------------------------
__global__ void __launch_bounds__(256) k_edges(
    const int* __restrict__ src, const int* __restrict__ dst, int nedges)
{
    const int lane = threadIdx.x & 31;
    const int sub  = lane >> 3;          // edge within group of 4
    const int q    = lane & 7;           // float4 quarter (8 * 4 = 32 ch)
    const int gw   = (blockIdx.x * blockDim.x + threadIdx.x) >> 5;
    const int nw   = (gridDim.x * blockDim.x) >> 5;

    for (int base = gw * 4; base < nedges; base += nw * 4) {
        const int e = base + sub;
        if (e >= nedges) break;
        const int s = __ldg(&src[e]);
        const int d = __ldg(&dst[e]);
        float ee = __ldg(&g_el[s]) + __ldg(&g_er[d]);
        ee = (ee >= 0.0f) ? ee : 0.01f * ee;
        const float p = __expf(ee);
        if (q == 0) atomicAdd(&g_esum[d], p);
        const float4 zv = __ldg(reinterpret_cast<const float4*>(g_z + s * OUT_DIM) + q);
        red_add_v4(g_hacc + d * OUT_DIM + q * 4,
                   make_float4(p * zv.x, p * zv.y, p * zv.z, p * zv.w));
    }
}

// ---------------------------------------------------------------------------
// K2b: invert esum once per node (removes 3.2M div.rn from k_final)
// ---------------------------------------------------------------------------
__global__ void k_inv(int n) {
    const int i = blockIdx.x * blockDim.x + threadIdx.x;
    if (i < n) {
        const float es = g_esum[i];
        g_esum[i] = (es > 0.0f) ? 1.0f / es : 0.0f;
    }
}

// ---------------------------------------------------------------------------
// K3: h_out = hacc * inv_esum; BN stats with block-level reduction.
// ---------------------------------------------------------------------------
__global__ void __launch_bounds__(256) k_final(float* __restrict__ out, int n)
{
    __shared__ float redbuf[2][8][32];
    const int lane = threadIdx.x & 31;
    const int wid  = threadIdx.x >> 5;
    const int total = n * OUT_DIM;
    const int stride = gridDim.x * blockDim.x;
    float s = 0.f, sq = 0.f;
    for (int i = blockIdx.x * blockDim.x + threadIdx.x; i < total; i += stride) {
        const int node = i >> 5;
        const float v = g_hacc[i] * g_esum[node];   // esum holds inverse
        out[i] = v;
        s += v;
        sq += v * v;
    }
    redbuf[0][wid][lane] = s;
    redbuf[1][wid][lane] = sq;
    __syncthreads();
    if (wid == 0) {
        float a = 0.f, b = 0.f;
        #pragma unroll
        for (int w = 0; w < 8; w++) { a += redbuf[0][w][lane]; b += redbuf[1][w][lane]; }
        atomicAdd(&g_stats[lane], a);
        atomicAdd(&g_stats[OUT_DIM + lane], b);
    }
}

// ---------------------------------------------------------------------------
// K4: fold stats into per-channel affine
// ---------------------------------------------------------------------------
__global__ void k_bn(const float* __restrict__ gamma,
                     const float* __restrict__ beta, int n)
{
    const int t = threadIdx.x;
    const float inv_n = 1.0f / (float)n;
    const float mean = g_stats[t] * inv_n;
    const float var  = g_stats[OUT_DIM + t] * inv_n - mean * mean;
    const float sc   = gamma[t] * rsqrtf(var + 1e-5f);
    g_bn[t] = sc;
    g_bn[OUT_DIM + t] = beta[t] - mean * sc;
}

// ---------------------------------------------------------------------------
// K5: BN affine + ELU, vectorized
// ---------------------------------------------------------------------------
__global__ void __launch_bounds__(256) k_elu(float* __restrict__ out, int n)
{
    const int total4 = (n * OUT_DIM) / 4;
    const int stride = gridDim.x * blockDim.x;
    float4* out4 = reinterpret_cast<float4*>(out);
    const float4* sc4 = reinterpret_cast<const float4*>(g_bn);
    const float4* sh4 = reinterpret_cast<const float4*>(g_bn + OUT_DIM);
    for (int i = blockIdx.x * blockDim.x + threadIdx.x; i < total4; i += stride) {
        const int g = i & 7;                   // float4 group within 32 channels
        const float4 sc = __ldg(&sc4[g]);
        const float4 sh = __ldg(&sh4[g]);
        float4 x = out4[i];
        x.x = fmaf(x.x, sc.x, sh.x);
        x.y = fmaf(x.y, sc.y, sh.y);
        x.z = fmaf(x.z, sc.z, sh.z);
        x.w = fmaf(x.w, sc.w, sh.w);
        x.x = (x.x > 0.f) ? x.x : expm1f(x.x);
        x.y = (x.y > 0.f) ? x.y : expm1f(x.y);
        x.z = (x.z > 0.f) ? x.z : expm1f(x.z);
        x.w = (x.w > 0.f) ? x.w : expm1f(x.w);
        out4[i] = x;
    }
}

// ---------------------------------------------------------------------------
extern "C" void kernel_launch(void* const* d_in, const int* in_sizes, int n_in,
                              void* d_out, int out_size)
{
    const float* h     = (const float*)d_in[0];
    const float* Wfc   = (const float*)d_in[1];
    const float* Wa    = (const float*)d_in[2];
    const float* gamma = (const float*)d_in[3];
    const float* beta  = (const float*)d_in[4];
    const int*   src   = (const int*)d_in[5];
    const int*   dst   = (const int*)d_in[6];

    const int n      = in_sizes[0] / IN_DIM;   // 100000
    const int nedges = in_sizes[5];            // 1600000
    float* out = (float*)d_out;

    k_zero <<<1024, 256>>>(n);
    k_gemm <<<1480, 256>>>(h, Wfc, Wa, n);
    k_edges<<<4096, 256>>>(src, dst, nedges);
    k_inv  <<<(n + 255) / 256, 256>>>(n);
    k_final<<<1024, 256>>>(out, n);
    k_bn   <<<1, OUT_DIM>>>(gamma, beta, n);
    k_elu  <<<1024, 256>>>(out, n);
}

// round 3
// speedup vs baseline: 1.8763x; 1.0144x over previous
#include <cuda_runtime.h>

#define IN_DIM 128
#define OUT_DIM 32
#define NMAX 100000

__device__ float g_z[NMAX * OUT_DIM];      // z = h @ W_fc
__device__ float g_el[NMAX];               // z @ a_l
__device__ float g_er[NMAX];               // z @ a_r
__device__ float g_esum[NMAX];             // sum exp(e) per dst
__device__ float g_hacc[NMAX * OUT_DIM];   // sum exp(e)*z[src] per dst
__device__ float g_stats[2 * OUT_DIM];     // channel sum, sumsq

__device__ __forceinline__ void red_add_v4(float* addr, float4 v) {
    asm volatile("red.global.add.v4.f32 [%0], {%1,%2,%3,%4};"
                 :: "l"(addr), "f"(v.x), "f"(v.y), "f"(v.z), "f"(v.w)
                 : "memory");
}

// ---------------------------------------------------------------------------
// K0: zero accumulators (vectorized)
// ---------------------------------------------------------------------------
__global__ void k_zero(int n) {
    const int total4 = (n * OUT_DIM) / 4;
    const int stride = gridDim.x * blockDim.x;
    float4 z4 = make_float4(0.f, 0.f, 0.f, 0.f);
    float4* hacc4 = reinterpret_cast<float4*>(g_hacc);
    for (int i = blockIdx.x * blockDim.x + threadIdx.x; i < total4; i += stride) {
        hacc4[i] = z4;
        if (i < n) g_esum[i] = 0.0f;
        if (i < 2 * OUT_DIM) g_stats[i] = 0.0f;
    }
}

// ---------------------------------------------------------------------------
// K1: z = h @ W_fc ; el = z@a_l ; er = z@a_r   (warp: 4 nodes, lane = col)
// ---------------------------------------------------------------------------
__global__ void __launch_bounds__(256) k_gemm(
    const float* __restrict__ h, const float* __restrict__ Wfc,
    const float* __restrict__ Wa, int n)
{
    __shared__ float Ws[IN_DIM * OUT_DIM];        // 16 KB
    __shared__ float4 hs4[8][4 * 32];             // 16 KB

    for (int i = threadIdx.x; i < IN_DIM * OUT_DIM; i += blockDim.x)
        Ws[i] = Wfc[i];
    __syncthreads();

    const int lane = threadIdx.x & 31;
    const int wid  = threadIdx.x >> 5;
    const int gw   = (blockIdx.x * blockDim.x + threadIdx.x) >> 5;
    const int nw   = (gridDim.x * blockDim.x) >> 5;

    const float al = Wa[lane];
    const float ar = Wa[OUT_DIM + lane];
    float4* hsw = hs4[wid];

    const int ngroups = (n + 3) >> 2;
    for (int g = gw; g < ngroups; g += nw) {
        const int base = g * 4;
        #pragma unroll
        for (int i = 0; i < 4; i++) {
            int node = base + i;
            if (node < n)
                hsw[i * 32 + lane] =
                    reinterpret_cast<const float4*>(h + (size_t)node * IN_DIM)[lane];
        }
        __syncwarp();

        float acc0 = 0.f, acc1 = 0.f, acc2 = 0.f, acc3 = 0.f;
        #pragma unroll 8
        for (int k4 = 0; k4 < 32; k4++) {
            const float w0 = Ws[(k4 * 4 + 0) * 32 + lane];
            const float w1 = Ws[(k4 * 4 + 1) * 32 + lane];
            const float w2 = Ws[(k4 * 4 + 2) * 32 + lane];
            const float w3 = Ws[(k4 * 4 + 3) * 32 + lane];
            const float4 h0 = hsw[0 * 32 + k4];
            const float4 h1 = hsw[1 * 32 + k4];
            const float4 h2 = hsw[2 * 32 + k4];
            const float4 h3 = hsw[3 * 32 + k4];
            acc0 = fmaf(h0.x, w0, acc0); acc0 = fmaf(h0.y, w1, acc0);
            acc0 = fmaf(h0.z, w2, acc0); acc0 = fmaf(h0.w, w3, acc0);
            acc1 = fmaf(h1.x, w0, acc1); acc1 = fmaf(h1.y, w1, acc1);
            acc1 = fmaf(h1.z, w2, acc1); acc1 = fmaf(h1.w, w3, acc1);
            acc2 = fmaf(h2.x, w0, acc2); acc2 = fmaf(h2.y, w1, acc2);
            acc2 = fmaf(h2.z, w2, acc2); acc2 = fmaf(h2.w, w3, acc2);
            acc3 = fmaf(h3.x, w0, acc3); acc3 = fmaf(h3.y, w1, acc3);
            acc3 = fmaf(h3.z, w2, acc3); acc3 = fmaf(h3.w, w3, acc3);
        }

        float zz[4] = {acc0, acc1, acc2, acc3};
        #pragma unroll
        for (int i = 0; i < 4; i++) {
            int node = base + i;
            if (node >= n) break;
            float z = zz[i];
            g_z[node * OUT_DIM + lane] = z;
            float vl = z * al;
            float vr = z * ar;
            #pragma unroll
            for (int off = 16; off; off >>= 1) {
                vl += __shfl_xor_sync(0xffffffffu, vl, off);
                vr += __shfl_xor_sync(0xffffffffu, vr, off);
            }
            if (lane == 0) { g_el[node] = vl; g_er[node] = vr; }
        }
        __syncwarp();
    }
}

// ---------------------------------------------------------------------------
// K2: edge pass, 8 edges per warp (2 per lane-group, interleaved for MLP).
// 8 lanes per edge, each lane owns a float4 quarter of the channel row.
// Unnormalized softmax accumulation (shift-invariance; |e| small).
// ---------------------------------------------------------------------------
__global__ void __launch_bounds__(256) k_edges(
    const int* __restrict__ src, const int* __restrict__ dst, int nedges)
{
    const int lane = threadIdx.x & 31;
    const int sub  = lane >> 3;          // edge slot 0..3
    const int q    = lane & 7;           // float4 quarter
    const int gw   = (blockIdx.x * blockDim.x + threadIdx.x) >> 5;
    const int nw   = (gridDim.x * blockDim.x) >> 5;

    for (int base = gw * 8; base < nedges; base += nw * 8) {
        const int e0 = base + sub;
        const int e1 = base + 4 + sub;
        const bool v0 = e0 < nedges;
        const bool v1 = e1 < nedges;

        int s0 = 0, d0 = 0, s1 = 0, d1 = 0;
        if (v0) { s0 = __ldg(&src[e0]); d0 = __ldg(&dst[e0]); }
        if (v1) { s1 = __ldg(&src[e1]); d1 = __ldg(&dst[e1]); }

        float ee0 = 0.f, ee1 = 0.f;
        if (v0) ee0 = __ldg(&g_el[s0]) + __ldg(&g_er[d0]);
        if (v1) ee1 = __ldg(&g_el[s1]) + __ldg(&g_er[d1]);
        ee0 = (ee0 >= 0.0f) ? ee0 : 0.01f * ee0;
        ee1 = (ee1 >= 0.0f) ? ee1 : 0.01f * ee1;
        const float p0 = __expf(ee0);
        const float p1 = __expf(ee1);

        float4 zv0, zv1;
        if (v0) zv0 = __ldg(reinterpret_cast<const float4*>(g_z + s0 * OUT_DIM) + q);
        if (v1) zv1 = __ldg(reinterpret_cast<const float4*>(g_z + s1 * OUT_DIM) + q);

        if (v0) {
            if (q == 0) atomicAdd(&g_esum[d0], p0);
            red_add_v4(g_hacc + d0 * OUT_DIM + q * 4,
                       make_float4(p0 * zv0.x, p0 * zv0.y, p0 * zv0.z, p0 * zv0.w));
        }
        if (v1) {
            if (q == 0) atomicAdd(&g_esum[d1], p1);
            red_add_v4(g_hacc + d1 * OUT_DIM + q * 4,
                       make_float4(p1 * zv1.x, p1 * zv1.y, p1 * zv1.z, p1 * zv1.w));
        }
    }
}

// ---------------------------------------------------------------------------
// K3: BN stats only (no out write). inv(esum) once per warp-iteration.
// ---------------------------------------------------------------------------
__global__ void __launch_bounds__(256) k_stats(int n)
{
    __shared__ float redbuf[2][8][32];
    const int lane = threadIdx.x & 31;
    const int wid  = threadIdx.x >> 5;
    const int total = n * OUT_DIM;
    const int stride = gridDim.x * blockDim.x;
    float s = 0.f, sq = 0.f;
    for (int i = blockIdx.x * blockDim.x + threadIdx.x; i < total; i += stride) {
        const int node = i >> 5;                    // all lanes: same node
        float inv = 0.0f;
        if (lane == 0) {
            const float es = g_esum[node];
            inv = (es > 0.0f) ? __frcp_rn(es) : 0.0f;
        }
        inv = __shfl_sync(0xffffffffu, inv, 0);
        const float v = g_hacc[i] * inv;
        s += v;
        sq += v * v;
    }
    redbuf[0][wid][lane] = s;
    redbuf[1][wid][lane] = sq;
    __syncthreads();
    if (wid == 0) {
        float a = 0.f, b = 0.f;
        #pragma unroll
        for (int w = 0; w < 8; w++) { a += redbuf[0][w][lane]; b += redbuf[1][w][lane]; }
        atomicAdd(&g_stats[lane], a);
        atomicAdd(&g_stats[OUT_DIM + lane], b);
    }
}

// ---------------------------------------------------------------------------
// K4: recompute v, apply BN affine + ELU, single out write.
// Per-block affine fold from g_stats (redundant, free).
// ---------------------------------------------------------------------------
__global__ void __launch_bounds__(256) k_elu(float* __restrict__ out,
                                             const float* __restrict__ gamma,
                                             const float* __restrict__ beta, int n)
{
    __shared__ float sc_s[OUT_DIM], sh_s[OUT_DIM];
    if (threadIdx.x < OUT_DIM) {
        const int t = threadIdx.x;
        const float inv_n = 1.0f / (float)n;
        const float mean = g_stats[t] * inv_n;
        const float var  = g_stats[OUT_DIM + t] * inv_n - mean * mean;
        const float sc   = gamma[t] * rsqrtf(var + 1e-5f);
        sc_s[t] = sc;
        sh_s[t] = beta[t] - mean * sc;
    }
    __syncthreads();

    const int lane = threadIdx.x & 31;
    const float sc = sc_s[lane];
    const float sh = sh_s[lane];
    const int total = n * OUT_DIM;
    const int stride = gridDim.x * blockDim.x;
    for (int i = blockIdx.x * blockDim.x + threadIdx.x; i < total; i += stride) {
        const int node = i >> 5;
        float inv = 0.0f;
        if (lane == 0) {
            const float es = g_esum[node];
            inv = (es > 0.0f) ? __frcp_rn(es) : 0.0f;
        }
        inv = __shfl_sync(0xffffffffu, inv, 0);
        const float x = fmaf(g_hacc[i] * inv, sc, sh);
        out[i] = (x > 0.0f) ? x : expm1f(x);
    }
}

// ---------------------------------------------------------------------------
extern "C" void kernel_launch(void* const* d_in, const int* in_sizes, int n_in,
                              void* d_out, int out_size)
{
    const float* h     = (const float*)d_in[0];
    const float* Wfc   = (const float*)d_in[1];
    const float* Wa    = (const float*)d_in[2];
    const float* gamma = (const float*)d_in[3];
    const float* beta  = (const float*)d_in[4];
    const int*   src   = (const int*)d_in[5];
    const int*   dst   = (const int*)d_in[6];

    const int n      = in_sizes[0] / IN_DIM;   // 100000
    const int nedges = in_sizes[5];            // 1600000
    float* out = (float*)d_out;

    k_zero <<<1024, 256>>>(n);
    k_gemm <<<1480, 256>>>(h, Wfc, Wa, n);
    k_edges<<<4096, 256>>>(src, dst, nedges);
    k_stats<<<1024, 256>>>(n);
    k_elu  <<<1024, 256>>>(out, gamma, beta, n);
}